// round 12
// baseline (speedup 1.0000x reference)
#include <cuda_runtime.h>
#include <math.h>
#include <string.h>

#define B_ 4
#define S_ 4096
#define H_ 2048
#define E_ 16
#define ED_ 512
#define H4 512               // 16-byte units per row
#define NBLK 512
#define ROWS_PER_BLK 32
#define BLKS_PER_BATCH 128   // NBLK / B_
#define NBLK_GEMV 256
#define NBLK_P2A 96

typedef unsigned long long ull;

// ---------------- device scratch ----------------
__device__ float g_part[NBLK * H_];        // per-block LN partial sums (4 MB)
__device__ float g_qi[B_ * H_];
__device__ float g_lf[E_ * H_];
__device__ float g_attp[NBLK_GEMV * B_ * E_];
__device__ int g_c1, g_c2, g_c3;           // zero-init; reset by epilogue

__device__ __forceinline__ float warp_sum(float v) {
#pragma unroll
    for (int o = 16; o > 0; o >>= 1) v += __shfl_xor_sync(0xffffffffu, v, o);
    return v;
}
__device__ __forceinline__ ull ffma2(ull a, ull b, ull c) {
    ull d;
    asm("fma.rn.f32x2 %0, %1, %2, %3;" : "=l"(d) : "l"(a), "l"(b), "l"(c));
    return d;
}
__device__ __forceinline__ ull add2(ull a, ull b) {
    ull d;
    asm("add.rn.f32x2 %0, %1, %2;" : "=l"(d) : "l"(a), "l"(b));
    return d;
}
__device__ __forceinline__ float pairsum(ull v) {
    float2 f; memcpy(&f, &v, 8);
    return f.x + f.y;
}
__device__ __forceinline__ ull pack2(float f) {
    float2 t = make_float2(f, f);
    ull r; memcpy(&r, &t, 8);
    return r;
}
__device__ __forceinline__ int ld_acq(int* p) {
    int v;
    asm volatile("ld.acquire.gpu.global.b32 %0, [%1];" : "=r"(v) : "l"(p) : "memory");
    return v;
}

// Shared memory overlay: phases are separated by block-level barriers.
union Smem {
    struct {                       // phase 1
        float2 ms[2][8];
        ulonglong2 acc[4][128];    // 8 KB
    } p1;
    struct {                       // phase 2a
        float4 q[8][32];
    } p2a;
    struct {                       // phase 2b
        ulonglong2 x[20 * 128];    // 40 KB x-chunk
        float attp[8][32];
        float qv[4][2][B_];
        float red[4][64];
        float att[64];
        float w[ED_];
        float eb[E_];
        float sb[E_];
    } p2b;
};

__global__ void __launch_bounds__(256, 4)
kFused(const float* __restrict__ hid, const float* __restrict__ le,
       const float* __restrict__ ce, const float* __restrict__ spatial,
       const float* __restrict__ edge, const float* __restrict__ gamma,
       const float* __restrict__ beta, const float* __restrict__ Wq,
       const float* __restrict__ bq, const float* __restrict__ Wk,
       const float* __restrict__ bk, const int* __restrict__ curp,
       const int* __restrict__ avail, float* __restrict__ out)
{
    __shared__ Smem su;
    __shared__ int s_last;
    const int tid = threadIdx.x, warp = tid >> 5, lane = tid & 31;
    const int blk = blockIdx.x;

    // ============ Phase 1: LN + mean-over-S partials (32 rows/block) ============
    {
        const int qt = warp & 3, rg = warp >> 2;
        const size_t row0 = (size_t)blk * ROWS_PER_BLK;
        const int colbase = qt * 128 + lane;
        const ulonglong2* base = reinterpret_cast<const ulonglong2*>(hid);
        const ulonglong2* p = base + (row0 + rg) * H4 + colbase;
        ulonglong2 v[4];
        ull acc[8];
#pragma unroll
        for (int i = 0; i < 8; i++) acc[i] = 0ull;
#pragma unroll
        for (int i = 0; i < 4; i++) v[i] = p[i * 32];

        for (int it = 0; it < 16; it++) {
            const ulonglong2* pn = p + ((it < 15) ? 2 * H4 : 0);
            ulonglong2 n0 = pn[0], n1 = pn[32], n2 = pn[64], n3 = pn[96];

            ull sp = 0ull, sq = 0ull;
#pragma unroll
            for (int i = 0; i < 4; i++) {
                sp = add2(sp, v[i].x); sp = add2(sp, v[i].y);
                sq = ffma2(v[i].x, v[i].x, sq);
                sq = ffma2(v[i].y, v[i].y, sq);
            }
            float s = warp_sum(pairsum(sp));
            float s2 = warp_sum(pairsum(sq));
            if (lane == 0) su.p1.ms[it & 1][warp] = make_float2(s, s2);
            __syncthreads();
            const float4* sm = reinterpret_cast<const float4*>(&su.p1.ms[it & 1][rg * 4]);
            float4 p0 = sm[0], p1 = sm[1];
            const float S  = p0.x + p0.z + p1.x + p1.z;
            const float S2 = p0.y + p0.w + p1.y + p1.w;
            const float mu = S * (1.f / H_);
            const float rr = rsqrtf(S2 * (1.f / H_) - mu * mu + 1e-5f);
            const ull rr2 = pack2(rr);
            const ull c2v = pack2(-mu * rr);
#pragma unroll
            for (int i = 0; i < 4; i++) {
                acc[2 * i]     = add2(ffma2(v[i].x, rr2, acc[2 * i]), c2v);
                acc[2 * i + 1] = add2(ffma2(v[i].y, rr2, acc[2 * i + 1]), c2v);
            }
            v[0] = n0; v[1] = n1; v[2] = n2; v[3] = n3;
            p = pn;
        }
        if (rg == 1) {
#pragma unroll
            for (int i = 0; i < 4; i++)
                su.p1.acc[qt][i * 32 + lane] = make_ulonglong2(acc[2 * i], acc[2 * i + 1]);
        }
        __syncthreads();
        if (rg == 0) {
            ulonglong2* o2 = reinterpret_cast<ulonglong2*>(g_part) + (size_t)blk * H4;
#pragma unroll
            for (int i = 0; i < 4; i++) {
                ulonglong2 b = su.p1.acc[qt][i * 32 + lane];
                o2[colbase + i * 32] =
                    make_ulonglong2(add2(acc[2 * i], b.x), add2(acc[2 * i + 1], b.y));
            }
        }
    }
    __threadfence();
    __syncthreads();
    if (tid == 0) atomicAdd(&g_c1, 1);

    if (blk >= NBLK_GEMV) return;   // blocks 256..511 done

    // ============ Phase 2a: qi reduce + lf build (blocks 0..95) ============
    if (blk < NBLK_P2A) {
        if (tid == 0) { while (ld_acq(&g_c1) < NBLK) {} }
        __syncthreads();
        if (blk < 64) {
            const int b = blk >> 4, chunk = blk & 15;
            const int h4i = chunk * 32 + lane;
            const float4* gp = reinterpret_cast<const float4*>(g_part);
            size_t basep = ((size_t)(b * BLKS_PER_BATCH + warp * 16)) * H4 + h4i;
            float4 s = make_float4(0.f, 0.f, 0.f, 0.f);
#pragma unroll
            for (int c = 0; c < 16; c++) {
                float4 t = gp[basep + (size_t)c * H4];
                s.x += t.x; s.y += t.y; s.z += t.z; s.w += t.w;
            }
            su.p2a.q[warp][lane] = s;
            __syncthreads();
            if (tid < 32) {
                float4 t = su.p2a.q[0][lane];
#pragma unroll
                for (int q = 1; q < 8; q++) {
                    float4 u = su.p2a.q[q][lane];
                    t.x += u.x; t.y += u.y; t.z += u.z; t.w += u.w;
                }
                const int cur = *curp;
                float4 g4 = reinterpret_cast<const float4*>(gamma)[h4i];
                float4 b4 = reinterpret_cast<const float4*>(beta)[h4i];
                float4 l4 = reinterpret_cast<const float4*>(le)[cur * H4 + h4i];
                float4 r;
                r.x = l4.x + g4.x * (t.x * (1.f / S_)) + b4.x;
                r.y = l4.y + g4.y * (t.y * (1.f / S_)) + b4.y;
                r.z = l4.z + g4.z * (t.z * (1.f / S_)) + b4.z;
                r.w = l4.w + g4.w * (t.w * (1.f / S_)) + b4.w;
                reinterpret_cast<float4*>(g_qi)[b * H4 + h4i] = r;
            }
        } else {
            int idx = (blk - 64) * 256 + tid;   // 0..8191 float4
            float4 a = reinterpret_cast<const float4*>(le)[idx];
            float4 c = reinterpret_cast<const float4*>(ce)[idx];
            reinterpret_cast<float4*>(g_lf)[idx] =
                make_float4(a.x + c.x, a.y + c.y, a.z + c.z, a.w + c.w);
        }
        __threadfence();
        __syncthreads();
        if (tid == 0) atomicAdd(&g_c2, 1);
    }

    // ============ Phase 2b: q/k GEMV (blocks 0..255) ============
    if (tid == 0) { while (ld_acq(&g_c2) < NBLK_P2A) {} }
    __syncthreads();

    const int half = warp & 1, pair = warp >> 1;
    const int j0 = blk * 8 + pair * 2;           // 2 columns per warp pair
    const int ebase = B_ + half * 8;

    ull aq0[B_], aq1[B_], ak0[8], ak1[8];
#pragma unroll
    for (int b = 0; b < B_; b++) { aq0[b] = 0ull; aq1[b] = 0ull; }
#pragma unroll
    for (int e = 0; e < 8; e++) { ak0[e] = 0ull; ak1[e] = 0ull; }

    const float4* qi4 = reinterpret_cast<const float4*>(g_qi);
    const float4* lf4 = reinterpret_cast<const float4*>(g_lf);
    const ulonglong2* wq0 = reinterpret_cast<const ulonglong2*>(Wq) + (size_t)j0 * H4;
    const ulonglong2* wq1 = wq0 + H4;
    const ulonglong2* wk0 = reinterpret_cast<const ulonglong2*>(Wk) + (size_t)j0 * H4;
    const ulonglong2* wk1 = wk0 + H4;
    float4* s_x4 = reinterpret_cast<float4*>(su.p2b.x);

    for (int c = 0; c < 4; c++) {
        __syncthreads();
#pragma unroll
        for (int i = 0; i < 10; i++) {
            int idx = i * 256 + tid;
            int row = idx >> 7, col = idx & 127;
            s_x4[idx] = (row < B_) ? qi4[row * H4 + c * 128 + col]
                                   : lf4[(row - B_) * H4 + c * 128 + col];
        }
        __syncthreads();
#pragma unroll
        for (int t = 0; t < 4; t++) {
            const int idx = t * 32 + lane;
            const int gidx = c * 128 + idx;
            ulonglong2 c0 = wk0[gidx], c1 = wk1[gidx];
            if (half == 0) {
                ulonglong2 a0 = wq0[gidx], a1 = wq1[gidx];
#pragma unroll
                for (int b = 0; b < B_; b++) {
                    ulonglong2 x = su.p2b.x[b * 128 + idx];
                    aq0[b] = ffma2(a0.x, x.x, aq0[b]); aq0[b] = ffma2(a0.y, x.y, aq0[b]);
                    aq1[b] = ffma2(a1.x, x.x, aq1[b]); aq1[b] = ffma2(a1.y, x.y, aq1[b]);
                }
            }
#pragma unroll
            for (int e = 0; e < 8; e++) {
                ulonglong2 x = su.p2b.x[(ebase + e) * 128 + idx];
                ak0[e] = ffma2(c0.x, x.x, ak0[e]); ak0[e] = ffma2(c0.y, x.y, ak0[e]);
                ak1[e] = ffma2(c1.x, x.x, ak1[e]); ak1[e] = ffma2(c1.y, x.y, ak1[e]);
            }
        }
    }
    // reductions + biases
    const float inv_sqrt_h = rsqrtf((float)H_);
    float k0v[8], k1v[8];
    {
        const float bk0 = bk[j0], bk1 = bk[j0 + 1];
#pragma unroll
        for (int e = 0; e < 8; e++) {
            k0v[e] = warp_sum(pairsum(ak0[e])) + bk0;
            k1v[e] = warp_sum(pairsum(ak1[e])) + bk1;
        }
    }
    if (half == 0) {
        const float bq0 = bq[j0], bq1 = bq[j0 + 1];
#pragma unroll
        for (int b = 0; b < B_; b++) {
            float q0 = warp_sum(pairsum(aq0[b])) + bq0;
            float q1 = warp_sum(pairsum(aq1[b])) + bq1;
            if (lane == 0) { su.p2b.qv[pair][0][b] = q0; su.p2b.qv[pair][1][b] = q1; }
        }
    }
    __syncthreads();
    if (lane == 0) {
#pragma unroll
        for (int b = 0; b < B_; b++) {
            float q0 = su.p2b.qv[pair][0][b], q1 = su.p2b.qv[pair][1][b];
#pragma unroll
            for (int e = 0; e < 8; e++)
                su.p2b.attp[warp][b * 8 + e] = (q0 * k0v[e] + q1 * k1v[e]) * inv_sqrt_h;
        }
    }
    __syncthreads();
    if (tid < B_ * E_) {
        int b = tid >> 4, e = tid & 15, hf = e >> 3, el = e & 7;
        float s = 0.f;
#pragma unroll
        for (int pr = 0; pr < 4; pr++) s += su.p2b.attp[pr * 2 + hf][b * 8 + el];
        g_attp[blk * (B_ * E_) + tid] = s;
    }
    __threadfence();
    __syncthreads();
    if (tid == 0) {
        int old = atomicAdd(&g_c3, 1);
        s_last = (old == NBLK_GEMV - 1) ? 1 : 0;
    }
    __syncthreads();
    if (!s_last) return;

    // ============ Epilogue (last GEMV block only, 256 threads) ============
    const int cur = *curp;
    {
        int o = tid & 63, qc = tid >> 6;   // 4 chunks of 64 blocks
        float s = 0.f;
#pragma unroll 8
        for (int c = 0; c < 64; c++) s += g_attp[(qc * 64 + c) * (B_ * E_) + o];
        su.p2b.red[qc][o] = s;
    }
    for (int h = tid; h < ED_; h += 256) {
        float a = 0.f;
#pragma unroll
        for (int i = 0; i < E_; i++) {
            int d = abs(i - cur);
            float rm = (float)avail[i] * ((i != cur) ? 1.f : 0.f) * (1.f / (float)max(d, 1));
            a += rm * edge[i * ED_ + h];
        }
        su.p2b.w[h] = a;
    }
    if (tid < E_) su.p2b.sb[tid] = spatial[abs(tid - cur)];
    __syncthreads();
    if (tid < B_ * E_)
        su.p2b.att[tid] = su.p2b.red[0][tid] + su.p2b.red[1][tid]
                        + su.p2b.red[2][tid] + su.p2b.red[3][tid];

    for (int jj = 0; jj < 2; jj++) {
        int je = warp * 2 + jj;
        float s = 0.f;
#pragma unroll
        for (int t = 0; t < 16; t++)
            s += su.p2b.w[t * 32 + lane] * edge[je * ED_ + t * 32 + lane];
        s = warp_sum(s);
        if (lane == 0) su.p2b.eb[je] = s;
    }
    __syncthreads();

    if (warp == 0) {
        float av = (lane < E_) ? (float)avail[lane] : 0.f;
        float num_avail = warp_sum(av);
        float tprob = 1.f / num_avail;
        float logt = logf(tprob);
        float klacc = 0.f;
        int nidx = 0;
        for (int b = 0; b < B_; b++) {
            float sc = -1e30f;
            if (lane < E_) {
                bool ok = (avail[lane] > 0);
                sc = su.p2b.att[b * E_ + lane] + su.p2b.sb[lane] + su.p2b.eb[lane];
                sc = ok ? sc : -1e9f;
            }
            float m = sc;
#pragma unroll
            for (int o = 8; o > 0; o >>= 1) m = fmaxf(m, __shfl_xor_sync(0xffffffffu, m, o, 16));
            float ex = (lane < E_) ? __expf(sc - m) : 0.f;
            float sum = ex;
#pragma unroll
            for (int o = 8; o > 0; o >>= 1) sum += __shfl_xor_sync(0xffffffffu, sum, o, 16);
            float p = (lane < E_) ? (ex / sum) : 0.f;
            if (lane < E_) out[1 + b * E_ + lane] = p;
            float ps = fmaxf(p, 1e-10f);
            if (lane < E_) klacc += tprob * (logt - logf(ps));
            if (b == 0) {
                float pm = (lane < E_) ? p : -1.f;
                float mm = pm;
#pragma unroll
                for (int o = 16; o > 0; o >>= 1) mm = fmaxf(mm, __shfl_xor_sync(0xffffffffu, mm, o));
                unsigned bal = __ballot_sync(0xffffffffu, pm == mm);
                nidx = __ffs(bal) - 1;
            }
        }
        float kl = warp_sum(klacc);
        if (lane == 0) {
            out[0] = (kl / (float)B_) * 0.01f;
            out[1 + B_ * E_] = (float)nidx;
            g_c1 = 0; g_c2 = 0; g_c3 = 0;   // reset for next graph replay
        }
    }
}

// ---------------- launch ----------------
extern "C" void kernel_launch(void* const* d_in, const int* in_sizes, int n_in,
                              void* d_out, int out_size) {
    const float* hid     = (const float*)d_in[0];
    const float* le      = (const float*)d_in[1];
    const float* ce      = (const float*)d_in[2];
    const float* spatial = (const float*)d_in[3];
    const float* edge    = (const float*)d_in[4];
    const float* gamma   = (const float*)d_in[5];
    const float* beta    = (const float*)d_in[6];
    const float* Wq      = (const float*)d_in[7];
    const float* bq      = (const float*)d_in[8];
    const float* Wk      = (const float*)d_in[9];
    const float* bk      = (const float*)d_in[10];
    // d_in[11], d_in[12] (Wv, bv) intentionally unused: v is dead in the reference
    const int*   curp    = (const int*)d_in[13];
    const int*   avail   = (const int*)d_in[14];
    float* out = (float*)d_out;

    kFused<<<NBLK, 256>>>(hid, le, ce, spatial, edge, gamma, beta,
                          Wq, bq, Wk, bk, curp, avail, out);
}